// round 16
// baseline (speedup 1.0000x reference)
#include <cuda_runtime.h>

#define HH 512
#define WW 512
#define NPIX (HH*WW)
#define NIMG 32
#define SMOOTHF 1e-5f
#define KF 5            // fused skeletonize iterations per pass
#define HALO_C 12       // column halo per side (>= 2*KF, multiple of 4)
#define OWNC 104        // owned columns per warp window (128 - 2*HALO_C)
#define CTILES 5        // ceil(512/104)
#define RB 128          // rows per band
#define NBANDS 4
#define LAGOUT 14       // output lag: 3*(KF-1)+2
#define NSTEPS 154      // RB + 25 + 1 (even, x0 = r0-11)
#define ALLM 0xffffffffu
#define NSKEL (2*NIMG*CTILES*NBANDS)   // 1280 skel blocks per pass
#define NDICE 8192                     // dice backfill blocks
#define NSDICE 8192                    // sdice backfill blocks
#define PROD_PER_BAND 10u              // 2 tensors * 5 col-tiles (pass2 -> sdice)
#define PROD_PER_IMG  20u              // CTILES * NBANDS pass-1 blocks per (img,tens)
// bid ranges (FIFO launch order): pass1 | dice | pass2 | sdice
#define BID_DICE   NSKEL
#define BID_PASS2  (NSKEL + NDICE)
#define BID_SDICE  (2*NSKEL + NDICE)
#define NBLK_TOTAL (2*NSKEL + NDICE + NSDICE)

// Scratch (device globals: no allocation allowed; zero-initialized at load)
__device__ float    g_tmp [2][NIMG*NPIX];   // after iterations 1..5
__device__ float    g_skel[2][NIMG*NPIX];   // after iterations 6..10
__device__ float    g_acc [NIMG][8];        // 0:sp 1:st 2:spt 3:ssp 4:sst 5:sspt
__device__ unsigned g_ctr;                  // sdice completion counter
__device__ unsigned g_done[NIMG][NBANDS];   // pass-2 producer flags (per img, band)
__device__ unsigned g_p1done[2][NIMG];      // pass-1 producer flags (per tens, img)

__device__ __forceinline__ float sigf(float x){
    return __fdividef(1.0f, 1.0f + __expf(-x));
}

// ---- plain-dice backfill path ----
__device__ __forceinline__ void dice_path(int idx, const float* __restrict__ logits,
                                          const float* __restrict__ target){
    int img   = idx >> 8;          // 256 warps per image
    int chunk = idx & 255;
    int lane  = threadIdx.x;
    const float4* Lp = (const float4*)(logits + (size_t)img*NPIX);
    const float4* Tp = (const float4*)(target + (size_t)img*NPIX);
    int base = chunk*256 + lane;
    float4 l[8], t[8];
    #pragma unroll
    for (int i = 0; i < 8; i++) l[i] = Lp[base + i*32];
    #pragma unroll
    for (int i = 0; i < 8; i++) t[i] = Tp[base + i*32];
    float sp=0.f, st=0.f, spt=0.f;
    #pragma unroll
    for (int i = 0; i < 8; i++){
        float p;
        p = sigf(l[i].x); sp += p; st += t[i].x; spt += p*t[i].x;
        p = sigf(l[i].y); sp += p; st += t[i].y; spt += p*t[i].y;
        p = sigf(l[i].z); sp += p; st += t[i].z; spt += p*t[i].z;
        p = sigf(l[i].w); sp += p; st += t[i].w; spt += p*t[i].w;
    }
    #pragma unroll
    for (int o=16;o;o>>=1){
        sp  += __shfl_down_sync(ALLM, sp , o);
        st  += __shfl_down_sync(ALLM, st , o);
        spt += __shfl_down_sync(ALLM, spt, o);
    }
    if (lane == 0){
        atomicAdd(&g_acc[img][0], sp);
        atomicAdd(&g_acc[img][1], st);
        atomicAdd(&g_acc[img][2], spt);
    }
}

// ---- skeleton-dice backfill path + finalize ----
__device__ __forceinline__ void sdice_path(int idx, float* __restrict__ out){
    int img   = idx >> 8;
    int chunk = idx & 255;          // 1024 px = rows [2*chunk, 2*chunk+1]
    int band  = chunk >> 6;         // both rows inside one 128-row band
    int lane  = threadIdx.x;

    if (lane == 0){
        while (atomicAdd(&g_done[img][band], 0u) < PROD_PER_BAND) __nanosleep(200);
    }
    __syncwarp();
    __threadfence();                // order data reads after the flag read

    const float4* Pp = (const float4*)(g_skel[0] + (size_t)img*NPIX);
    const float4* Tp = (const float4*)(g_skel[1] + (size_t)img*NPIX);
    int base = chunk*256 + lane;
    float4 p[8], t[8];
    #pragma unroll
    for (int i = 0; i < 8; i++) p[i] = Pp[base + i*32];
    #pragma unroll
    for (int i = 0; i < 8; i++) t[i] = Tp[base + i*32];
    float sp=0.f, st=0.f, spt=0.f;
    #pragma unroll
    for (int i = 0; i < 8; i++){
        sp  += (p[i].x+p[i].y)+(p[i].z+p[i].w);
        st  += (t[i].x+t[i].y)+(t[i].z+t[i].w);
        spt += (p[i].x*t[i].x + p[i].y*t[i].y) + (p[i].z*t[i].z + p[i].w*t[i].w);
    }
    #pragma unroll
    for (int o=16;o;o>>=1){
        sp  += __shfl_down_sync(ALLM, sp , o);
        st  += __shfl_down_sync(ALLM, st , o);
        spt += __shfl_down_sync(ALLM, spt, o);
    }
    if (lane == 0){
        atomicAdd(&g_acc[img][3], sp);
        atomicAdd(&g_acc[img][4], st);
        atomicAdd(&g_acc[img][5], spt);
    }

    // last-block finalize
    __threadfence();
    unsigned old = 0;
    if (lane == 0) old = atomicAdd(&g_ctr, 1u);
    old = __shfl_sync(ALLM, old, 0);
    if (old == NSDICE - 1u){
        volatile float* a = &g_acc[lane][0];   // lane = image
        float d  = (2.0f*a[2] + SMOOTHF) / (a[0] + a[1] + SMOOTHF);
        float sd = (2.0f*a[5] + SMOOTHF) / (a[3] + a[4] + SMOOTHF);
        #pragma unroll
        for (int o=16;o;o>>=1){
            d  += __shfl_down_sync(ALLM, d , o);
            sd += __shfl_down_sync(ALLM, sd, o);
        }
        if (lane == 0){
            float dice  = d  * (1.0f/32.0f);
            float sdice = sd * (1.0f/32.0f);
            out[0] = 0.5f*(1.0f - dice) + 0.5f*(1.0f - sdice);
            out[1] = dice;
            out[2] = sdice;
        }
        // reset for next graph replay (globals start zeroed at module load,
        // so the invariant "all counters/accumulators == 0 on entry" holds)
        #pragma unroll
        for (int v = 0; v < 8; v++) g_acc[lane][v] = 0.0f;
        #pragma unroll
        for (int b = 0; b < NBANDS; b++) g_done[lane][b] = 0u;
        g_p1done[0][lane] = 0u;
        g_p1done[1][lane] = 0u;
        if (lane == 0) g_ctr = 0u;
    }
}

// One decoupled pipeline stage j (see prior rounds for the derivation).
// FMODE (compile-time literal): 2 = full row+col forcing of the eroded
// field, 1 = column-only forcing (rows provably in-image), 0 = no forcing
// (all lanes in-image AND rows in-image; predicates statically dead).
#define STAGE_G(j, sN, sO, eN, eO, CIN, OUT, FMODE)                           \
{                                                                             \
    float vm0 = fminf(sO[j][0], fminf(sN[j][0], CIN[0]));                     \
    float vm1 = fminf(sO[j][1], fminf(sN[j][1], CIN[1]));                     \
    float vm2 = fminf(sO[j][2], fminf(sN[j][2], CIN[2]));                     \
    float vm3 = fminf(sO[j][3], fminf(sN[j][3], CIN[3]));                     \
    float Lm = __shfl_up_sync  (ALLM, vm3, 1);                                \
    float Rm = __shfl_down_sync(ALLM, vm0, 1);                                \
    float m01 = fminf(vm0, vm1), m12 = fminf(vm1, vm2), m23 = fminf(vm2, vm3);\
    float en0 = fminf(Lm,  m01);                                              \
    float en1 = fminf(m01, vm2);                                              \
    float en2 = fminf(m12, vm3);                                              \
    float en3 = fminf(m23, Rm);                                               \
    if ((FMODE) == 2){                                                        \
        if (!(colok && (unsigned)(x - 3*(j) - 1) < (unsigned)HH)){            \
            en0 = NINF; en1 = NINF; en2 = NINF; en3 = NINF;                   \
        }                                                                     \
    } else if ((FMODE) == 1){                                                 \
        if (!colok){                                                          \
            en0 = NINF; en1 = NINF; en2 = NINF; en3 = NINF;                   \
        }                                                                     \
    }                                                                         \
    float tx0 = fmaxf(eO[j][0], fmaxf(eN[j][0], en0));                        \
    float tx1 = fmaxf(eO[j][1], fmaxf(eN[j][1], en1));                        \
    float tx2 = fmaxf(eO[j][2], fmaxf(eN[j][2], en2));                        \
    float tx3 = fmaxf(eO[j][3], fmaxf(eN[j][3], en3));                        \
    float Lx = __shfl_up_sync  (ALLM, tx3, 1);                                \
    float Rx = __shfl_down_sync(ALLM, tx0, 1);                                \
    float M01 = fmaxf(tx0, tx1), M12 = fmaxf(tx1, tx2), M23 = fmaxf(tx2, tx3);\
    float T0 = fmaxf(Lx,  M01);                                               \
    float T1 = fmaxf(M01, tx2);                                               \
    float T2 = fmaxf(M12, tx3);                                               \
    float T3 = fmaxf(M23, Rx);                                                \
    float o0 = fmaf(eN[j][0]-sO[j][0], T0, sO[j][0]);                         \
    float o1 = fmaf(eN[j][1]-sO[j][1], T1, sO[j][1]);                         \
    float o2 = fmaf(eN[j][2]-sO[j][2], T2, sO[j][2]);                         \
    float o3 = fmaf(eN[j][3]-sO[j][3], T3, sO[j][3]);                         \
    sO[j][0] = CIN[0]; sO[j][1] = CIN[1]; sO[j][2] = CIN[2]; sO[j][3] = CIN[3];\
    eO[j][0] = en0;    eO[j][1] = en1;    eO[j][2] = en2;    eO[j][3] = en3;  \
    OUT[0] = o0; OUT[1] = o1; OUT[2] = o2; OUT[3] = o3;                       \
}

// One full row-step. DOSIG / FMODE constant-fold per call site.
#define DO_STEP_G(X, sN, sO, eN, eO, DOSIG, FMODE)                            \
{                                                                             \
    int x = (X);                                                              \
    float in0[4] = {nxt[0], nxt[1], nxt[2], nxt[3]};                          \
    int xn = x + 1;                                                           \
    if (colok && (unsigned)xn < (unsigned)HH){                                \
        float4 t4 = *(const float4*)(src + (size_t)xn*WW + gc);               \
        if (DOSIG){                                                           \
            t4.x = sigf(t4.x); t4.y = sigf(t4.y);                             \
            t4.z = sigf(t4.z); t4.w = sigf(t4.w);                             \
        }                                                                     \
        nxt[0]=t4.x; nxt[1]=t4.y; nxt[2]=t4.z; nxt[3]=t4.w;                   \
    } else {                                                                  \
        nxt[0]=PINF; nxt[1]=PINF; nxt[2]=PINF; nxt[3]=PINF;                   \
    }                                                                         \
    float o4[4];                                                              \
    STAGE_G(4, sN, sO, eN, eO, b3,  o4, FMODE);                               \
    STAGE_G(3, sN, sO, eN, eO, b2,  b3, FMODE);                               \
    STAGE_G(2, sN, sO, eN, eO, b1,  b2, FMODE);                               \
    STAGE_G(1, sN, sO, eN, eO, b0,  b1, FMODE);                               \
    STAGE_G(0, sN, sO, eN, eO, in0, b0, FMODE);                               \
    if (owned && (unsigned)(x - LAGOUT - r0) < (unsigned)RB){                 \
        *(float4*)(dst + (size_t)(x - LAGOUT)*WW + gc) =                      \
            make_float4(o4[0], o4[1], o4[2], o4[3]);                          \
    }                                                                         \
}

#define STEP_PAIR(FMODE, DOSIG)                                               \
    DO_STEP_G(x0 + stp,     sA, sB, eA, eB, DOSIG, FMODE);                    \
    DO_STEP_G(x0 + stp + 1, sB, sA, eB, eA, DOSIG, FMODE);

// Shared skel prologue + segmented loop. Rows are provably in-image for all
// stages when 13 <= x <= 512: band 0 needs full checks only for steps < 24,
// band NBANDS-1 only for steps >= 140, interior bands never. Columns are
// all-in-image for ct in {1..3}. Segment boundaries (24, 140) are even, so
// the 2-step ping-pong unroll is preserved across segments.
#define SKEL_BODY(SRC_EXPR, DST_EXPR, DOSIG)                                  \
    int r0 = band * RB;                                                       \
    int c0 = ct*OWNC - HALO_C;                                                \
    int gc = c0 + (lane<<2);                                                  \
    bool colok = (gc >= 0) && (gc < WW);                                      \
    bool owned = (lane >= HALO_C/4) && (lane < (HALO_C+OWNC)/4) && colok;     \
    const float* __restrict__ src = (SRC_EXPR);                               \
    float* __restrict__ dst = (DST_EXPR);                                     \
    float sA[KF][4], sB[KF][4], eA[KF][4], eB[KF][4];                         \
    float b0[4], b1[4], b2[4], b3[4];                                         \
    _Pragma("unroll")                                                         \
    for (int j = 0; j < KF; j++)                                              \
        _Pragma("unroll")                                                     \
        for (int v = 0; v < 4; v++){                                          \
            sA[j][v]=PINF; sB[j][v]=PINF; eA[j][v]=NINF; eB[j][v]=NINF;       \
        }                                                                     \
    _Pragma("unroll")                                                         \
    for (int v = 0; v < 4; v++){ b0[v]=PINF; b1[v]=PINF; b2[v]=PINF; b3[v]=PINF; } \
    int x0 = r0 - 11;                                                         \
    float nxt[4];                                                             \
    if (colok && (unsigned)x0 < (unsigned)HH){                                \
        float4 t4 = *(const float4*)(src + (size_t)x0*WW + gc);               \
        if (DOSIG){                                                           \
            t4.x = sigf(t4.x); t4.y = sigf(t4.y);                             \
            t4.z = sigf(t4.z); t4.w = sigf(t4.w);                             \
        }                                                                     \
        nxt[0]=t4.x; nxt[1]=t4.y; nxt[2]=t4.z; nxt[3]=t4.w;                   \
    } else {                                                                  \
        nxt[0]=PINF; nxt[1]=PINF; nxt[2]=PINF; nxt[3]=PINF;                   \
    }                                                                         \
    bool allok = (ct >= 1) && (ct <= CTILES-2);                               \
    int chkpre  = (band == 0)        ? 24  : 0;                               \
    int chkpost = (band == NBANDS-1) ? 140 : NSTEPS;                          \
    int stp = 0;                                                              \
    for (; stp < chkpre; stp += 2){ STEP_PAIR(2, DOSIG) }                     \
    if (allok){                                                               \
        for (; stp < chkpost; stp += 2){ STEP_PAIR(0, DOSIG) }                \
    } else {                                                                  \
        for (; stp < chkpost; stp += 2){ STEP_PAIR(1, DOSIG) }                \
    }                                                                         \
    for (; stp < NSTEPS; stp += 2){ STEP_PAIR(2, DOSIG) }

// ---------------- single fused launch: pass1 | dice | pass2 | sdice --------
__global__ void __launch_bounds__(32, 12) k_all(const float* __restrict__ logits,
                                                const float* __restrict__ target,
                                                float* __restrict__ out){
    const float PINF = __int_as_float(0x7f800000);
    const float NINF = __int_as_float(0xff800000);

    int gw   = blockIdx.x;
    int lane = threadIdx.x;

    if (gw < NSKEL){
        // ---- pass 1: iterations 1..5 ----
        int band = gw & 3;  int q = gw >> 2;
        int ct   = q % CTILES; q /= CTILES;
        int img  = q & 31;  int tens = q >> 5;
        {
            SKEL_BODY((tens ? target : logits) + (size_t)img*NPIX,
                      g_tmp[tens] + (size_t)img*NPIX,
                      (tens == 0))
        }
        // publish: release = fence + atomic per (tens, img)
        __threadfence();
        if (lane == 0) atomicAdd(&g_p1done[tens][img], 1u);
    } else if (gw < BID_PASS2){
        // ---- plain-dice backfill ----
        dice_path(gw - BID_DICE, logits, target);
    } else if (gw < BID_SDICE){
        // ---- pass 2: iterations 6..10 (waits for its (tens,img) inputs) ----
        int idx  = gw - BID_PASS2;
        int band = idx & 3;  int q = idx >> 2;
        int ct   = q % CTILES; q /= CTILES;
        int img  = q & 31;  int tens = q >> 5;

        if (lane == 0){
            while (atomicAdd(&g_p1done[tens][img], 0u) < PROD_PER_IMG) __nanosleep(200);
        }
        __syncwarp();
        __threadfence();            // order g_tmp reads after the flag read
        {
            SKEL_BODY(g_tmp[tens] + (size_t)img*NPIX,
                      g_skel[tens] + (size_t)img*NPIX,
                      0)
        }
        // publish completion for this (img, band)
        __threadfence();
        if (lane == 0) atomicAdd(&g_done[img][band], 1u);
    } else {
        // ---- skeleton-dice backfill + finalize ----
        sdice_path(gw - BID_SDICE, out);
    }
}

extern "C" void kernel_launch(void* const* d_in, const int* in_sizes, int n_in,
                              void* d_out, int out_size){
    const float* logits = (const float*)d_in[0];
    const float* target = (const float*)d_in[1];
    float* out = (float*)d_out;

    k_all<<<NBLK_TOTAL, 32>>>(logits, target, out);
    (void)in_sizes; (void)n_in; (void)out_size;
}

// round 17
// speedup vs baseline: 1.2071x; 1.2071x over previous
#include <cuda_runtime.h>

#define HH 512
#define WW 512
#define NPIX (HH*WW)
#define NIMG 32
#define SMOOTHF 1e-5f
#define KF 5            // fused skeletonize iterations per pass
#define HALO_C 12       // column halo per side (>= 2*KF, multiple of 4)
#define OWNC 104        // owned columns per warp window (128 - 2*HALO_C)
#define CTILES 5        // ceil(512/104)
#define RB 128          // rows per band
#define NBANDS 4
#define LAGOUT 14       // output lag: 3*(KF-1)+2
#define NSTEPS 154      // RB + 25 + 1 (even, x0 = r0-11)
#define ALLM 0xffffffffu
#define NSKEL (2*NIMG*CTILES*NBANDS)   // 1280 skel blocks per pass
#define NDICE 8192                     // dice backfill blocks
#define NSDICE 8192                    // sdice backfill blocks
#define PROD_PER_BAND 10u              // 2 tensors * 5 col-tiles
#define PROD_PER_IMG  20u              // CTILES * NBANDS pass-1 blocks per (img,tens)
// bid ranges (FIFO launch order): pass1 | dice | pass2 | sdice
#define BID_DICE   NSKEL
#define BID_PASS2  (NSKEL + NDICE)
#define BID_SDICE  (2*NSKEL + NDICE)
#define NBLK_TOTAL (2*NSKEL + NDICE + NSDICE)

// Scratch (device globals: no allocation allowed; zero-initialized at load)
__device__ float    g_tmp [2][NIMG*NPIX];   // after iterations 1..5
__device__ float    g_skel[2][NIMG*NPIX];   // after iterations 6..10
__device__ float    g_acc [NIMG][8];        // 0:sp 1:st 2:spt 3:ssp 4:sst 5:sspt
__device__ unsigned g_ctr;                  // sdice completion counter
__device__ unsigned g_done[NIMG][NBANDS];   // pass-2 producer flags (per img, band)
__device__ unsigned g_p1done[2][NIMG];      // pass-1 producer flags (per tens, img)

__device__ __forceinline__ float sigf(float x){
    return __fdividef(1.0f, 1.0f + __expf(-x));
}

// ---- plain-dice backfill path ----
// One warp handles 1024 contiguous pixels of one image: 8 float4 per lane.
__device__ __forceinline__ void dice_path(int idx, const float* __restrict__ logits,
                                          const float* __restrict__ target){
    int img   = idx >> 8;          // 256 warps per image
    int chunk = idx & 255;
    int lane  = threadIdx.x;
    const float4* Lp = (const float4*)(logits + (size_t)img*NPIX);
    const float4* Tp = (const float4*)(target + (size_t)img*NPIX);
    int base = chunk*256 + lane;
    float4 l[8], t[8];
    #pragma unroll
    for (int i = 0; i < 8; i++) l[i] = Lp[base + i*32];
    #pragma unroll
    for (int i = 0; i < 8; i++) t[i] = Tp[base + i*32];
    float sp=0.f, st=0.f, spt=0.f;
    #pragma unroll
    for (int i = 0; i < 8; i++){
        float p;
        p = sigf(l[i].x); sp += p; st += t[i].x; spt += p*t[i].x;
        p = sigf(l[i].y); sp += p; st += t[i].y; spt += p*t[i].y;
        p = sigf(l[i].z); sp += p; st += t[i].z; spt += p*t[i].z;
        p = sigf(l[i].w); sp += p; st += t[i].w; spt += p*t[i].w;
    }
    #pragma unroll
    for (int o=16;o;o>>=1){
        sp  += __shfl_down_sync(ALLM, sp , o);
        st  += __shfl_down_sync(ALLM, st , o);
        spt += __shfl_down_sync(ALLM, spt, o);
    }
    if (lane == 0){
        atomicAdd(&g_acc[img][0], sp);
        atomicAdd(&g_acc[img][1], st);
        atomicAdd(&g_acc[img][2], spt);
    }
}

// ---- skeleton-dice backfill path ----
// Spins until its band's 10 pass-2 producer blocks have published g_skel,
// then accumulates; the last of NSDICE blocks finalizes the 3 outputs and
// resets all globals for the next graph replay.
__device__ __forceinline__ void sdice_path(int idx, float* __restrict__ out){
    int img   = idx >> 8;
    int chunk = idx & 255;          // 1024 px = rows [2*chunk, 2*chunk+1]
    int band  = chunk >> 6;         // both rows inside one 128-row band
    int lane  = threadIdx.x;

    if (lane == 0){
        while (atomicAdd(&g_done[img][band], 0u) < PROD_PER_BAND) __nanosleep(200);
    }
    __syncwarp();
    __threadfence();                // order data reads after the flag read

    const float4* Pp = (const float4*)(g_skel[0] + (size_t)img*NPIX);
    const float4* Tp = (const float4*)(g_skel[1] + (size_t)img*NPIX);
    int base = chunk*256 + lane;
    float4 p[8], t[8];
    #pragma unroll
    for (int i = 0; i < 8; i++) p[i] = Pp[base + i*32];
    #pragma unroll
    for (int i = 0; i < 8; i++) t[i] = Tp[base + i*32];
    float sp=0.f, st=0.f, spt=0.f;
    #pragma unroll
    for (int i = 0; i < 8; i++){
        sp  += (p[i].x+p[i].y)+(p[i].z+p[i].w);
        st  += (t[i].x+t[i].y)+(t[i].z+t[i].w);
        spt += (p[i].x*t[i].x + p[i].y*t[i].y) + (p[i].z*t[i].z + p[i].w*t[i].w);
    }
    #pragma unroll
    for (int o=16;o;o>>=1){
        sp  += __shfl_down_sync(ALLM, sp , o);
        st  += __shfl_down_sync(ALLM, st , o);
        spt += __shfl_down_sync(ALLM, spt, o);
    }
    if (lane == 0){
        atomicAdd(&g_acc[img][3], sp);
        atomicAdd(&g_acc[img][4], st);
        atomicAdd(&g_acc[img][5], spt);
    }

    // last-block finalize (all other atomics are ordered before the counter
    // increments by the threadfences).
    __threadfence();
    unsigned old = 0;
    if (lane == 0) old = atomicAdd(&g_ctr, 1u);
    old = __shfl_sync(ALLM, old, 0);
    if (old == NSDICE - 1u){
        volatile float* a = &g_acc[lane][0];   // lane = image
        float d  = (2.0f*a[2] + SMOOTHF) / (a[0] + a[1] + SMOOTHF);
        float sd = (2.0f*a[5] + SMOOTHF) / (a[3] + a[4] + SMOOTHF);
        #pragma unroll
        for (int o=16;o;o>>=1){
            d  += __shfl_down_sync(ALLM, d , o);
            sd += __shfl_down_sync(ALLM, sd, o);
        }
        if (lane == 0){
            float dice  = d  * (1.0f/32.0f);
            float sdice = sd * (1.0f/32.0f);
            out[0] = 0.5f*(1.0f - dice) + 0.5f*(1.0f - sdice);
            out[1] = dice;
            out[2] = sdice;
        }
        // reset for next graph replay (globals start zeroed at module load,
        // so the invariant "all counters/accumulators == 0 on entry" holds)
        #pragma unroll
        for (int v = 0; v < 8; v++) g_acc[lane][v] = 0.0f;
        #pragma unroll
        for (int b = 0; b < NBANDS; b++) g_done[lane][b] = 0u;
        g_p1done[0][lane] = 0u;
        g_p1done[1][lane] = 0u;
        if (lane == 0) g_ctr = 0u;
    }
}

// One decoupled pipeline stage j. Fed row xr = x - 3j (value in CIN).
// State: sN[j] = In_j[xr-1], sO[j] = In_j[xr-2], eN[j] = E_j[xr-2],
// eO[j] = E_j[xr-3]. Computes E_j[xr-1] and O_j[xr-2] -> OUT.
// Rotation by role swap (zero MOVs). Output is NOT boundary-forced: at
// OOB rows/cols it becomes +INF or NaN; fminf/fmaxf drop NaN operands, so
// downstream min chains treat it exactly as the +INF sentinel. Only the
// eroded field needs explicit forcing (en -> -INF at OOB), since it feeds
// a max-pool where the neutral element differs.
#define STAGE(j, sN, sO, eN, eO, CIN, OUT)                                    \
{                                                                             \
    float vm0 = fminf(sO[j][0], fminf(sN[j][0], CIN[0]));                     \
    float vm1 = fminf(sO[j][1], fminf(sN[j][1], CIN[1]));                     \
    float vm2 = fminf(sO[j][2], fminf(sN[j][2], CIN[2]));                     \
    float vm3 = fminf(sO[j][3], fminf(sN[j][3], CIN[3]));                     \
    float Lm = __shfl_up_sync  (ALLM, vm3, 1);                                \
    float Rm = __shfl_down_sync(ALLM, vm0, 1);                                \
    float m01 = fminf(vm0, vm1), m12 = fminf(vm1, vm2), m23 = fminf(vm2, vm3);\
    float en0 = fminf(Lm,  m01);                                              \
    float en1 = fminf(m01, vm2);                                              \
    float en2 = fminf(m12, vm3);                                              \
    float en3 = fminf(m23, Rm);                                               \
    if (!(colok && (unsigned)(x - 3*(j) - 1) < (unsigned)HH)){                \
        en0 = NINF; en1 = NINF; en2 = NINF; en3 = NINF;                       \
    }                                                                         \
    float tx0 = fmaxf(eO[j][0], fmaxf(eN[j][0], en0));                        \
    float tx1 = fmaxf(eO[j][1], fmaxf(eN[j][1], en1));                        \
    float tx2 = fmaxf(eO[j][2], fmaxf(eN[j][2], en2));                        \
    float tx3 = fmaxf(eO[j][3], fmaxf(eN[j][3], en3));                        \
    float Lx = __shfl_up_sync  (ALLM, tx3, 1);                                \
    float Rx = __shfl_down_sync(ALLM, tx0, 1);                                \
    float M01 = fmaxf(tx0, tx1), M12 = fmaxf(tx1, tx2), M23 = fmaxf(tx2, tx3);\
    float T0 = fmaxf(Lx,  M01);                                               \
    float T1 = fmaxf(M01, tx2);                                               \
    float T2 = fmaxf(M12, tx3);                                               \
    float T3 = fmaxf(M23, Rx);                                                \
    float o0 = fmaf(eN[j][0]-sO[j][0], T0, sO[j][0]);                         \
    float o1 = fmaf(eN[j][1]-sO[j][1], T1, sO[j][1]);                         \
    float o2 = fmaf(eN[j][2]-sO[j][2], T2, sO[j][2]);                         \
    float o3 = fmaf(eN[j][3]-sO[j][3], T3, sO[j][3]);                         \
    sO[j][0] = CIN[0]; sO[j][1] = CIN[1]; sO[j][2] = CIN[2]; sO[j][3] = CIN[3];\
    eO[j][0] = en0;    eO[j][1] = en1;    eO[j][2] = en2;    eO[j][3] = en3;  \
    OUT[0] = o0; OUT[1] = o1; OUT[2] = o2; OUT[3] = o3;                       \
}

// One full row-step (proven body). DOSIG constant-folds per call site.
#define DO_STEP(X, sN, sO, eN, eO, DOSIG)                                     \
{                                                                             \
    int x = (X);                                                              \
    float in0[4] = {nxt[0], nxt[1], nxt[2], nxt[3]};                          \
    int xn = x + 1;                                                           \
    if (colok && (unsigned)xn < (unsigned)HH){                                \
        float4 t4 = *(const float4*)(src + (size_t)xn*WW + gc);               \
        if (DOSIG){                                                           \
            t4.x = sigf(t4.x); t4.y = sigf(t4.y);                             \
            t4.z = sigf(t4.z); t4.w = sigf(t4.w);                             \
        }                                                                     \
        nxt[0]=t4.x; nxt[1]=t4.y; nxt[2]=t4.z; nxt[3]=t4.w;                   \
    } else {                                                                  \
        nxt[0]=PINF; nxt[1]=PINF; nxt[2]=PINF; nxt[3]=PINF;                   \
    }                                                                         \
    float o4[4];                                                              \
    STAGE(4, sN, sO, eN, eO, b3,  o4);                                        \
    STAGE(3, sN, sO, eN, eO, b2,  b3);                                        \
    STAGE(2, sN, sO, eN, eO, b1,  b2);                                        \
    STAGE(1, sN, sO, eN, eO, b0,  b1);                                        \
    STAGE(0, sN, sO, eN, eO, in0, b0);                                        \
    if (owned && (unsigned)(x - LAGOUT - r0) < (unsigned)RB){                 \
        *(float4*)(dst + (size_t)(x - LAGOUT)*WW + gc) =                      \
            make_float4(o4[0], o4[1], o4[2], o4[3]);                          \
    }                                                                         \
}

// Shared skel prologue/loop body.
#define SKEL_BODY(SRC_EXPR, DST_EXPR, DOSIG)                                  \
    int r0 = band * RB;                                                       \
    int c0 = ct*OWNC - HALO_C;                                                \
    int gc = c0 + (lane<<2);                                                  \
    bool colok = (gc >= 0) && (gc < WW);                                      \
    bool owned = (lane >= HALO_C/4) && (lane < (HALO_C+OWNC)/4) && colok;     \
    const float* __restrict__ src = (SRC_EXPR);                               \
    float* __restrict__ dst = (DST_EXPR);                                     \
    float sA[KF][4], sB[KF][4], eA[KF][4], eB[KF][4];                         \
    float b0[4], b1[4], b2[4], b3[4];                                         \
    _Pragma("unroll")                                                         \
    for (int j = 0; j < KF; j++)                                              \
        _Pragma("unroll")                                                     \
        for (int v = 0; v < 4; v++){                                          \
            sA[j][v]=PINF; sB[j][v]=PINF; eA[j][v]=NINF; eB[j][v]=NINF;       \
        }                                                                     \
    _Pragma("unroll")                                                         \
    for (int v = 0; v < 4; v++){ b0[v]=PINF; b1[v]=PINF; b2[v]=PINF; b3[v]=PINF; } \
    int x0 = r0 - 11;                                                         \
    float nxt[4];                                                             \
    if (colok && (unsigned)x0 < (unsigned)HH){                                \
        float4 t4 = *(const float4*)(src + (size_t)x0*WW + gc);               \
        if (DOSIG){                                                           \
            t4.x = sigf(t4.x); t4.y = sigf(t4.y);                             \
            t4.z = sigf(t4.z); t4.w = sigf(t4.w);                             \
        }                                                                     \
        nxt[0]=t4.x; nxt[1]=t4.y; nxt[2]=t4.z; nxt[3]=t4.w;                   \
    } else {                                                                  \
        nxt[0]=PINF; nxt[1]=PINF; nxt[2]=PINF; nxt[3]=PINF;                   \
    }                                                                         \
    for (int step = 0; step < NSTEPS; step += 2){                             \
        DO_STEP(x0 + step,     sA, sB, eA, eB, DOSIG);                        \
        DO_STEP(x0 + step + 1, sB, sA, eB, eA, DOSIG);                        \
    }

// ---------------- single fused launch: pass1 | dice | pass2 | sdice --------
__global__ void __launch_bounds__(32, 12) k_all(const float* __restrict__ logits,
                                                const float* __restrict__ target,
                                                float* __restrict__ out){
    const float PINF = __int_as_float(0x7f800000);
    const float NINF = __int_as_float(0xff800000);

    int gw   = blockIdx.x;
    int lane = threadIdx.x;

    if (gw < NSKEL){
        // ---- pass 1: iterations 1..5 ----
        int band = gw & 3;  int q = gw >> 2;
        int ct   = q % CTILES; q /= CTILES;
        int img  = q & 31;  int tens = q >> 5;
        {
            SKEL_BODY((tens ? target : logits) + (size_t)img*NPIX,
                      g_tmp[tens] + (size_t)img*NPIX,
                      (tens == 0))
        }
        // publish: release = fence + atomic per (tens, img)
        __threadfence();
        if (lane == 0) atomicAdd(&g_p1done[tens][img], 1u);
    } else if (gw < BID_PASS2){
        // ---- plain-dice backfill ----
        dice_path(gw - BID_DICE, logits, target);
    } else if (gw < BID_SDICE){
        // ---- pass 2: iterations 6..10 (waits for its (tens,img) inputs) ----
        int idx  = gw - BID_PASS2;
        int band = idx & 3;  int q = idx >> 2;
        int ct   = q % CTILES; q /= CTILES;
        int img  = q & 31;  int tens = q >> 5;

        if (lane == 0){
            while (atomicAdd(&g_p1done[tens][img], 0u) < PROD_PER_IMG) __nanosleep(200);
        }
        __syncwarp();
        __threadfence();            // order g_tmp reads after the flag read
        {
            SKEL_BODY(g_tmp[tens] + (size_t)img*NPIX,
                      g_skel[tens] + (size_t)img*NPIX,
                      0)
        }
        // publish completion for this (img, band)
        __threadfence();
        if (lane == 0) atomicAdd(&g_done[img][band], 1u);
    } else {
        // ---- skeleton-dice backfill + finalize ----
        sdice_path(gw - BID_SDICE, out);
    }
}

extern "C" void kernel_launch(void* const* d_in, const int* in_sizes, int n_in,
                              void* d_out, int out_size){
    const float* logits = (const float*)d_in[0];
    const float* target = (const float*)d_in[1];
    float* out = (float*)d_out;

    k_all<<<NBLK_TOTAL, 32>>>(logits, target, out);
    (void)in_sizes; (void)n_in; (void)out_size;
}